// round 2
// baseline (speedup 1.0000x reference)
#include <cuda_runtime.h>
#include <cuda_bf16.h>
#include <float.h>
#include <math.h>

// Problem constants
#define BB 8
#define LL 200
#define DD 256
#define HH 8
#define HS 32
#define HB 64          // H*B
#define KTOP 20
#define NROW 1600      // B*L
#define LNELEM 409600  // B*L*D

// ---------------- device scratch (no allocs allowed) ----------------
__device__ float g_a[NROW * DD];            // seqs @ conv1_w.T + b1   [B,L,D]
__device__ float g_b[NROW * DD];            // seqs @ conv2_w.T + b2   [B,L,D]
__device__ float g_w[NROW * DD];            // seqs @ W_w.T + W_b      [B,L,D]
__device__ float g_raw[(size_t)HB * LL * LL];       // raw_graph (masked) 10.24MB
__device__ unsigned char g_sel[(size_t)HB * LL * LL]; // topk symmetric mask 2.56MB
__device__ unsigned char g_mask[LL * LL];   // attention mask as u8

// ---------------- mask dtype detect + convert ----------------
// attention_mask serialized dtype unknown (bool/u8, int32, or float32).
// Byte-pattern probe on the first 40000 bytes (safe for all 3 dtypes since
// the mask is ~30% ones): u8 -> nonzero at offset%4==1; int32(1) -> only
// offset%4==0; float32(1.0f)=00 00 80 3F -> offsets 2,3.
__global__ void mask_kernel(const void* __restrict__ src) {
    __shared__ int flags[4];
    int t = threadIdx.x;
    if (t < 4) flags[t] = 0;
    __syncthreads();
    const unsigned char* p = (const unsigned char*)src;
    for (int i = t; i < LL * LL; i += 256) {
        if (p[i]) flags[i & 3] = 1;
    }
    __syncthreads();
    int dt;  // 0=u8, 1=i32, 2=f32
    if (flags[1]) dt = 0;
    else if (flags[2] | flags[3]) dt = 2;
    else dt = 1;
    for (int i = t; i < LL * LL; i += 256) {
        unsigned char m;
        if (dt == 0)      m = (p[i] != 0);
        else if (dt == 1) m = (((const int*)src)[i] != 0);
        else              m = (((const float*)src)[i] != 0.0f);
        g_mask[i] = m;
    }
}

// ---------------- zero the sel array (graph replays re-run everything) ----
__global__ void zero_sel_kernel() {
    size_t i = (size_t)blockIdx.x * 256 + threadIdx.x;
    if (i < ((size_t)HB * LL * LL) / 4) ((unsigned int*)g_sel)[i] = 0;
}

// ---------------- 3 fused GEMMs: out = X @ W.T + bias ----------------
// X [1600,256], W [256,256] row-major (out_dim major), 64x64 tile, 4x4/thread.
__global__ void gemm3_kernel(const float* __restrict__ X,
                             const float* __restrict__ W0, const float* __restrict__ B0,
                             const float* __restrict__ W1, const float* __restrict__ B1,
                             const float* __restrict__ W2, const float* __restrict__ B2) {
    const float* W; const float* Bv; float* O;
    if (blockIdx.z == 0)      { W = W0; Bv = B0; O = g_a; }
    else if (blockIdx.z == 1) { W = W1; Bv = B1; O = g_b; }
    else                      { W = W2; Bv = B2; O = g_w; }

    __shared__ float As[16][68];
    __shared__ float Bs[16][68];
    int i0 = blockIdx.y * 64;
    int o0 = blockIdx.x * 64;
    int t = threadIdx.x;
    int tx = t & 15, ty = t >> 4;
    int lr = t >> 2;           // 0..63 : row within tile for loads
    int lc4 = (t & 3) * 4;     // k sub-offset for float4 loads

    float acc[4][4];
#pragma unroll
    for (int i = 0; i < 4; i++)
#pragma unroll
        for (int j = 0; j < 4; j++) acc[i][j] = 0.f;

    for (int k0 = 0; k0 < DD; k0 += 16) {
        float4 xa = *(const float4*)&X[(size_t)(i0 + lr) * DD + k0 + lc4];
        float4 wb = *(const float4*)&W[(size_t)(o0 + lr) * DD + k0 + lc4];
        As[lc4 + 0][lr] = xa.x; As[lc4 + 1][lr] = xa.y;
        As[lc4 + 2][lr] = xa.z; As[lc4 + 3][lr] = xa.w;
        Bs[lc4 + 0][lr] = wb.x; Bs[lc4 + 1][lr] = wb.y;
        Bs[lc4 + 2][lr] = wb.z; Bs[lc4 + 3][lr] = wb.w;
        __syncthreads();
#pragma unroll
        for (int kk = 0; kk < 16; kk++) {
            float4 a4 = *(const float4*)&As[kk][ty * 4];
            float4 b4 = *(const float4*)&Bs[kk][tx * 4];
            float am[4] = {a4.x, a4.y, a4.z, a4.w};
            float bn[4] = {b4.x, b4.y, b4.z, b4.w};
#pragma unroll
            for (int mi = 0; mi < 4; mi++)
#pragma unroll
                for (int ni = 0; ni < 4; ni++) acc[mi][ni] += am[mi] * bn[ni];
        }
        __syncthreads();
    }
#pragma unroll
    for (int mi = 0; mi < 4; mi++) {
#pragma unroll
        for (int ni = 0; ni < 4; ni++) {
            int oo = o0 + tx * 4 + ni;
            O[(size_t)(i0 + ty * 4 + mi) * DD + oo] = acc[mi][ni] + Bv[oo];
        }
    }
}

// ---------------- Pass 1: raw_graph, single full read of time_matrices ----
// Block = (q, b), 256 threads: warp h owns head h. Within a warp, lanes split
// into 4 groups of 8 (ksub = lane/8 handles k-base+ksub; j8 = lane%8 covers
// HS=32 via float4). att = sum a*(b+ti); den = ||a|| * ||b+ti|| + 1e-6.
__global__ void raw_kernel(const float* __restrict__ tm) {
    int q = blockIdx.x, b = blockIdx.y;
    int t = threadIdx.x, h = t >> 5, lane = t & 31;
    int ksub = lane >> 3, j8 = lane & 7;
    __shared__ float sbuf[8][32];

    const float* arow = g_a + (size_t)(b * LL + q) * DD + h * HS + j8 * 4;
    float4 a4 = *(const float4*)arow;
    float s = a4.x * a4.x + a4.y * a4.y + a4.z * a4.z + a4.w * a4.w;
#pragma unroll
    for (int off = 4; off; off >>= 1) s += __shfl_xor_sync(0xffffffffu, s, off);
    float a2 = sqrtf(s);

    const float* tibase = tm + (size_t)(b * LL + q) * LL * DD + h * HS + j8 * 4;
    const float* bbase  = g_b + (size_t)b * LL * DD + h * HS + j8 * 4;
    size_t rowbase = (size_t)((h * BB + b) * LL + q) * LL;
    const unsigned char* mrow = g_mask + q * LL;

    for (int k0 = 0; k0 < LL; k0 += 32) {
        int kend = min(LL, k0 + 32);
        for (int kb = k0; kb < kend; kb += 4) {
            int k = kb + ksub;
            float4 tv = *(const float4*)(tibase + (size_t)k * DD);
            float4 bv = *(const float4*)(bbase + (size_t)k * DD);
            float c0 = bv.x + tv.x, c1 = bv.y + tv.y;
            float c2 = bv.z + tv.z, c3 = bv.w + tv.w;
            float s1 = a4.x * c0 + a4.y * c1 + a4.z * c2 + a4.w * c3;
            float s2 = c0 * c0 + c1 * c1 + c2 * c2 + c3 * c3;
#pragma unroll
            for (int off = 4; off; off >>= 1) {
                s1 += __shfl_xor_sync(0xffffffffu, s1, off);
                s2 += __shfl_xor_sync(0xffffffffu, s2, off);
            }
            if (j8 == 0) {
                float raw = s1 / (a2 * sqrtf(s2) + 1e-6f);
                if (mrow[k]) raw = 0.f;
                sbuf[h][k - k0] = raw;
            }
        }
        __syncwarp();
        if (lane < kend - k0) g_raw[rowbase + k0 + lane] = sbuf[h][lane];
        __syncwarp();
    }
}

// ---------------- Top-K with jax.lax.top_k tie semantics -----------------
// One warp per (hb,q) row. 20 iterations of argmax; ties -> lower index
// (stable, matches XLA TopK). Symmetric scatter into g_sel (racing writes of
// the identical value 1 are benign).
__global__ void topk_kernel() {
    int w = threadIdx.x >> 5, lane = threadIdx.x & 31;
    int row = blockIdx.x * 8 + w;                 // 0..12799 = hb*200+q
    size_t base = (size_t)row * LL;
    float v[7];
#pragma unroll
    for (int i = 0; i < 7; i++) {
        int g = lane + i * 32;
        v[i] = (g < LL) ? g_raw[base + g] : -FLT_MAX;
    }
    int hb = row / LL, q = row - hb * LL;
    for (int it = 0; it < KTOP; it++) {
        float bv = -FLT_MAX;
        int bi = 1 << 30;
#pragma unroll
        for (int i = 0; i < 7; i++) {
            if (v[i] > bv) { bv = v[i]; bi = lane + i * 32; }
        }
#pragma unroll
        for (int off = 16; off; off >>= 1) {
            float ov = __shfl_xor_sync(0xffffffffu, bv, off);
            int   oi = __shfl_xor_sync(0xffffffffu, bi, off);
            if (ov > bv || (ov == bv && oi < bi)) { bv = ov; bi = oi; }
        }
        if (lane == (bi & 31)) v[bi >> 5] = -FLT_MAX;
        if (lane == 0) {
            g_sel[base + bi] = 1;
            g_sel[((size_t)hb * LL + bi) * LL + q] = 1;
        }
    }
}

// ---------------- Pass 2: sparse matmuls + from_heads + LayerNorm --------
// Block = (q, b), 256 threads: thread t = h*32+j produces output dim d=t of
// outputs[b,q,:] and time_outputs[b,q,:]. ti is only gathered at selected k.
__global__ void out_kernel(const float* __restrict__ tm,
                           const float* __restrict__ gamma,
                           const float* __restrict__ beta,
                           float* __restrict__ out, int out_size) {
    int q = blockIdx.x, b = blockIdx.y;
    int t = threadIdx.x, h = t >> 5, lane = t & 31;
    int hb = h * BB + b;
    __shared__ float s_raw[8][LL];
    __shared__ unsigned char s_sel[8][LL];
    __shared__ float rs[8];

    size_t base = (size_t)(hb * LL + q) * LL;
    for (int i = lane; i < LL; i += 32) {
        s_raw[h][i] = g_raw[base + i];
        s_sel[h][i] = g_sel[base + i];
    }
    __syncwarp();

    const float* tirow = tm + (size_t)(b * LL + q) * LL * DD + t;
    const float* wcol  = g_w + (size_t)b * LL * DD + t;
    float acc_o = 0.f, acc_t = 0.f;
#pragma unroll 4
    for (int k = 0; k < LL; k++) {
        if (s_sel[h][k]) {
            float r = s_raw[h][k];
            acc_o += r * wcol[(size_t)k * DD];
            acc_t += r * tirow[(size_t)k * DD];
        }
    }

    // LayerNorm over the 256 outputs of this block (two-pass for stability)
    float sum = acc_o;
#pragma unroll
    for (int off = 16; off; off >>= 1) sum += __shfl_xor_sync(0xffffffffu, sum, off);
    if (lane == 0) rs[h] = sum;
    __syncthreads();
    float tot = 0.f;
#pragma unroll
    for (int i = 0; i < 8; i++) tot += rs[i];
    float mu = tot * (1.f / 256.f);
    __syncthreads();

    float d = acc_o - mu;
    float sq = d * d;
#pragma unroll
    for (int off = 16; off; off >>= 1) sq += __shfl_xor_sync(0xffffffffu, sq, off);
    if (lane == 0) rs[h] = sq;
    __syncthreads();
    float totq = 0.f;
#pragma unroll
    for (int i = 0; i < 8; i++) totq += rs[i];
    float var = totq * (1.f / 256.f);

    float ln = d * rsqrtf(var + 1e-8f) * gamma[t] + beta[t];
    size_t o = (size_t)(b * LL + q) * DD + t;
    out[o] = ln;
    if (out_size > LNELEM) out[LNELEM + o] = acc_t;
}

// ---------------- launch ----------------
extern "C" void kernel_launch(void* const* d_in, const int* in_sizes, int n_in,
                              void* d_out, int out_size) {
    const float* seqs    = (const float*)d_in[0];
    const void*  amask   = d_in[1];
    const float* tm      = (const float*)d_in[2];
    const float* conv1_w = (const float*)d_in[3];
    const float* conv1_b = (const float*)d_in[4];
    const float* conv2_w = (const float*)d_in[5];
    const float* conv2_b = (const float*)d_in[6];
    const float* W_w     = (const float*)d_in[7];
    const float* W_b     = (const float*)d_in[8];
    const float* ln_g    = (const float*)d_in[9];
    const float* ln_b    = (const float*)d_in[10];
    float* out = (float*)d_out;

    mask_kernel<<<1, 256>>>(amask);
    zero_sel_kernel<<<2500, 256>>>();
    gemm3_kernel<<<dim3(DD / 64, NROW / 64, 3), 256>>>(
        seqs, conv1_w, conv1_b, conv2_w, conv2_b, W_w, W_b);
    raw_kernel<<<dim3(LL, BB), 256>>>(tm);
    topk_kernel<<<HB * LL / 8, 256>>>();
    out_kernel<<<dim3(LL, BB), 256>>>(tm, ln_g, ln_b, out, out_size);
}

// round 4
// speedup vs baseline: 1.2360x; 1.2360x over previous
#include <cuda_runtime.h>
#include <cuda_bf16.h>
#include <float.h>
#include <math.h>

// Problem constants
#define BB 8
#define LL 200
#define DD 256
#define HH 8
#define HS 32
#define HB 64          // H*B
#define KTOP 20
#define NROW 1600      // B*L
#define LNELEM 409600  // B*L*D

// ---------------- device scratch (no allocs allowed) ----------------
__device__ float g_a[NROW * DD];            // seqs @ conv1_w.T + b1   [B,L,D]
__device__ float g_b[NROW * DD];            // seqs @ conv2_w.T + b2   [B,L,D]
__device__ float g_w[NROW * DD];            // seqs @ W_w.T + W_b      [B,L,D]
__device__ float g_raw[(size_t)HB * LL * LL];         // raw_graph (masked)
__device__ unsigned char g_sel[(size_t)HB * LL * LL]; // topk symmetric mask
__device__ unsigned char g_mask[LL * LL];   // attention mask as u8

// ---------------- mask dtype detect + convert ----------------
__global__ void mask_kernel(const void* __restrict__ src) {
    __shared__ int flags[4];
    int t = threadIdx.x;
    if (t < 4) flags[t] = 0;
    __syncthreads();
    const unsigned char* p = (const unsigned char*)src;
    for (int i = t; i < LL * LL; i += 256) {
        if (p[i]) flags[i & 3] = 1;
    }
    __syncthreads();
    int dt;  // 0=u8, 1=i32, 2=f32
    if (flags[1]) dt = 0;
    else if (flags[2] | flags[3]) dt = 2;
    else dt = 1;
    for (int i = t; i < LL * LL; i += 256) {
        unsigned char m;
        if (dt == 0)      m = (p[i] != 0);
        else if (dt == 1) m = (((const int*)src)[i] != 0);
        else              m = (((const float*)src)[i] != 0.0f);
        g_mask[i] = m;
    }
}

// ---------------- zero the sel array ----------------
__global__ void zero_sel_kernel() {
    size_t i = (size_t)blockIdx.x * 256 + threadIdx.x;
    if (i < ((size_t)HB * LL * LL) / 4) ((unsigned int*)g_sel)[i] = 0;
}

// ---------------- 3 fused GEMMs: out = X @ W.T + bias ----------------
__global__ void gemm3_kernel(const float* __restrict__ X,
                             const float* __restrict__ W0, const float* __restrict__ B0,
                             const float* __restrict__ W1, const float* __restrict__ B1,
                             const float* __restrict__ W2, const float* __restrict__ B2) {
    const float* W; const float* Bv; float* O;
    if (blockIdx.z == 0)      { W = W0; Bv = B0; O = g_a; }
    else if (blockIdx.z == 1) { W = W1; Bv = B1; O = g_b; }
    else                      { W = W2; Bv = B2; O = g_w; }

    __shared__ float As[16][68];
    __shared__ float Bs[16][68];
    int i0 = blockIdx.y * 64;
    int o0 = blockIdx.x * 64;
    int t = threadIdx.x;
    int tx = t & 15, ty = t >> 4;
    int lr = t >> 2;
    int lc4 = (t & 3) * 4;

    float acc[4][4];
#pragma unroll
    for (int i = 0; i < 4; i++)
#pragma unroll
        for (int j = 0; j < 4; j++) acc[i][j] = 0.f;

    for (int k0 = 0; k0 < DD; k0 += 16) {
        float4 xa = *(const float4*)&X[(size_t)(i0 + lr) * DD + k0 + lc4];
        float4 wb = *(const float4*)&W[(size_t)(o0 + lr) * DD + k0 + lc4];
        As[lc4 + 0][lr] = xa.x; As[lc4 + 1][lr] = xa.y;
        As[lc4 + 2][lr] = xa.z; As[lc4 + 3][lr] = xa.w;
        Bs[lc4 + 0][lr] = wb.x; Bs[lc4 + 1][lr] = wb.y;
        Bs[lc4 + 2][lr] = wb.z; Bs[lc4 + 3][lr] = wb.w;
        __syncthreads();
#pragma unroll
        for (int kk = 0; kk < 16; kk++) {
            float4 a4 = *(const float4*)&As[kk][ty * 4];
            float4 b4 = *(const float4*)&Bs[kk][tx * 4];
            float am[4] = {a4.x, a4.y, a4.z, a4.w};
            float bn[4] = {b4.x, b4.y, b4.z, b4.w};
#pragma unroll
            for (int mi = 0; mi < 4; mi++)
#pragma unroll
                for (int ni = 0; ni < 4; ni++) acc[mi][ni] += am[mi] * bn[ni];
        }
        __syncthreads();
    }
#pragma unroll
    for (int mi = 0; mi < 4; mi++) {
#pragma unroll
        for (int ni = 0; ni < 4; ni++) {
            int oo = o0 + tx * 4 + ni;
            O[(size_t)(i0 + ty * 4 + mi) * DD + oo] = acc[mi][ni] + Bv[oo];
        }
    }
}

// ---------------- Pass 1 + fused top-K -----------------------------------
// Block = (q, b), 256 threads: warp h owns head h and produces the full row
// raw_graph[hb, q, :] into smem. 8 k per iteration (4 independent float4
// load pairs in flight per lane). Then each warp runs the 20-step argmax
// top-K on its smem row and scatters the symmetric selection to g_sel.
__global__ void raw_kernel(const float* __restrict__ tm) {
    int q = blockIdx.x, b = blockIdx.y;
    int t = threadIdx.x, h = t >> 5, lane = t & 31;
    int ksub = lane >> 3, j8 = lane & 7;
    __shared__ float s_row[8][LL];

    const float* arow = g_a + (size_t)(b * LL + q) * DD + h * HS + j8 * 4;
    float4 a4 = *(const float4*)arow;
    float s = a4.x * a4.x + a4.y * a4.y + a4.z * a4.z + a4.w * a4.w;
#pragma unroll
    for (int off = 4; off; off >>= 1) s += __shfl_xor_sync(0xffffffffu, s, off);
    float a2 = sqrtf(s);

    const float* tibase = tm + (size_t)(b * LL + q) * LL * DD + h * HS + j8 * 4;
    const float* bbase  = g_b + (size_t)b * LL * DD + h * HS + j8 * 4;
    int hb = h * BB + b;
    size_t rowbase = (size_t)(hb * LL + q) * LL;
    const unsigned char* mrow = g_mask + q * LL;

    for (int kb = 0; kb < LL; kb += 8) {
        int ka = kb + ksub;
        int kc = kb + 4 + ksub;
        // 4 independent loads issued up front
        float4 ta = *(const float4*)(tibase + (size_t)ka * DD);
        float4 tc = *(const float4*)(tibase + (size_t)kc * DD);
        float4 ba = *(const float4*)(bbase + (size_t)ka * DD);
        float4 bc = *(const float4*)(bbase + (size_t)kc * DD);

        float c0 = ba.x + ta.x, c1 = ba.y + ta.y, c2 = ba.z + ta.z, c3 = ba.w + ta.w;
        float s1a = a4.x * c0 + a4.y * c1 + a4.z * c2 + a4.w * c3;
        float s2a = c0 * c0 + c1 * c1 + c2 * c2 + c3 * c3;
        float d0 = bc.x + tc.x, d1 = bc.y + tc.y, d2 = bc.z + tc.z, d3 = bc.w + tc.w;
        float s1b = a4.x * d0 + a4.y * d1 + a4.z * d2 + a4.w * d3;
        float s2b = d0 * d0 + d1 * d1 + d2 * d2 + d3 * d3;
#pragma unroll
        for (int off = 4; off; off >>= 1) {
            s1a += __shfl_xor_sync(0xffffffffu, s1a, off);
            s2a += __shfl_xor_sync(0xffffffffu, s2a, off);
            s1b += __shfl_xor_sync(0xffffffffu, s1b, off);
            s2b += __shfl_xor_sync(0xffffffffu, s2b, off);
        }
        if (j8 == 0) {
            float ra = s1a / (a2 * sqrtf(s2a) + 1e-6f);
            if (mrow[ka]) ra = 0.f;
            s_row[h][ka] = ra;
            float rb = s1b / (a2 * sqrtf(s2b) + 1e-6f);
            if (mrow[kc]) rb = 0.f;
            s_row[h][kc] = rb;
        }
    }
    __syncwarp();

    // write the row to global (coalesced) for pass 2
    for (int i = lane; i < LL; i += 32) g_raw[rowbase + i] = s_row[h][i];

    // ---- fused top-K (jax.lax.top_k tie semantics: ties -> lower index) ----
    float v[7];
#pragma unroll
    for (int i = 0; i < 7; i++) {
        int g = lane + i * 32;
        v[i] = (g < LL) ? s_row[h][g] : -FLT_MAX;
    }
    for (int it = 0; it < KTOP; it++) {
        float bv = -FLT_MAX;
        int bi = 1 << 30;
#pragma unroll
        for (int i = 0; i < 7; i++) {
            if (v[i] > bv) { bv = v[i]; bi = lane + i * 32; }
        }
#pragma unroll
        for (int off = 16; off; off >>= 1) {
            float ov = __shfl_xor_sync(0xffffffffu, bv, off);
            int   oi = __shfl_xor_sync(0xffffffffu, bi, off);
            if (ov > bv || (ov == bv && oi < bi)) { bv = ov; bi = oi; }
        }
        if (lane == (bi & 31)) v[bi >> 5] = -FLT_MAX;
        if (lane == 0) {
            g_sel[rowbase + bi] = 1;
            g_sel[((size_t)hb * LL + bi) * LL + q] = 1;
        }
    }
}

// ---------------- Pass 2: compacted sparse matmuls + LayerNorm -----------
// Block = (q, b). Phase 1: warp h ballot-compacts its sel row into an smem
// (index, value) list. Phase 2: branch-free unrolled gather loop -> high MLP.
__global__ void out_kernel(const float* __restrict__ tm,
                           const float* __restrict__ gamma,
                           const float* __restrict__ beta,
                           float* __restrict__ out, int out_size) {
    int q = blockIdx.x, b = blockIdx.y;
    int t = threadIdx.x, h = t >> 5, lane = t & 31;
    int hb = h * BB + b;
    __shared__ short s_idx[8][LL];
    __shared__ float s_val[8][LL];
    __shared__ float rs[8];

    size_t base = (size_t)(hb * LL + q) * LL;
    int cnt = 0;
#pragma unroll
    for (int c = 0; c < 7; c++) {
        int i = c * 32 + lane;
        bool pred = (i < LL) && g_sel[base + i];
        unsigned m = __ballot_sync(0xffffffffu, pred);
        if (pred) {
            int pos = cnt + __popc(m & ((1u << lane) - 1));
            s_idx[h][pos] = (short)i;
            s_val[h][pos] = g_raw[base + i];
        }
        cnt += __popc(m);
    }
    __syncwarp();

    const float* tirow = tm + (size_t)(b * LL + q) * LL * DD + t;
    const float* wcol  = g_w + (size_t)b * LL * DD + t;
    float acc_o = 0.f, acc_t = 0.f;
#pragma unroll 4
    for (int p = 0; p < cnt; p++) {
        int k = s_idx[h][p];
        float r = s_val[h][p];
        acc_o += r * wcol[(size_t)k * DD];
        acc_t += r * tirow[(size_t)k * DD];
    }

    // LayerNorm over the 256 outputs of this block
    float sum = acc_o;
#pragma unroll
    for (int off = 16; off; off >>= 1) sum += __shfl_xor_sync(0xffffffffu, sum, off);
    if (lane == 0) rs[h] = sum;
    __syncthreads();
    float tot = 0.f;
#pragma unroll
    for (int i = 0; i < 8; i++) tot += rs[i];
    float mu = tot * (1.f / 256.f);
    __syncthreads();

    float d = acc_o - mu;
    float sq = d * d;
#pragma unroll
    for (int off = 16; off; off >>= 1) sq += __shfl_xor_sync(0xffffffffu, sq, off);
    if (lane == 0) rs[h] = sq;
    __syncthreads();
    float totq = 0.f;
#pragma unroll
    for (int i = 0; i < 8; i++) totq += rs[i];
    float var = totq * (1.f / 256.f);

    float ln = d * rsqrtf(var + 1e-8f) * gamma[t] + beta[t];
    size_t o = (size_t)(b * LL + q) * DD + t;
    out[o] = ln;
    if (out_size > LNELEM) out[LNELEM + o] = acc_t;
}

// ---------------- launch ----------------
extern "C" void kernel_launch(void* const* d_in, const int* in_sizes, int n_in,
                              void* d_out, int out_size) {
    const float* seqs    = (const float*)d_in[0];
    const void*  amask   = d_in[1];
    const float* tm      = (const float*)d_in[2];
    const float* conv1_w = (const float*)d_in[3];
    const float* conv1_b = (const float*)d_in[4];
    const float* conv2_w = (const float*)d_in[5];
    const float* conv2_b = (const float*)d_in[6];
    const float* W_w     = (const float*)d_in[7];
    const float* W_b     = (const float*)d_in[8];
    const float* ln_g    = (const float*)d_in[9];
    const float* ln_b    = (const float*)d_in[10];
    float* out = (float*)d_out;

    mask_kernel<<<1, 256>>>(amask);
    zero_sel_kernel<<<2500, 256>>>();
    gemm3_kernel<<<dim3(DD / 64, NROW / 64, 3), 256>>>(
        seqs, conv1_w, conv1_b, conv2_w, conv2_b, W_w, W_b);
    raw_kernel<<<dim3(LL, BB), 256>>>(tm);
    out_kernel<<<dim3(LL, BB), 256>>>(tm, ln_g, ln_b, out, out_size);
}